// round 15
// baseline (speedup 1.0000x reference)
#include <cuda_runtime.h>
#include <math.h>

#define Hh 128
#define CB 32
#define DUPW 68
#define NTHREADS 256
#define NBLOCKS 128

// Output layout (concatenated return tuple, float32):
// decoder_output (4096,100,4) | dec_hidden (4,4096,128) | encoder_output (4096,64,128) | enc_hidden (4,4096,128) | loss (1)
#define DEC_OUT_OFF 0ul
#define DEC_HID_OFF 1638400ul
#define ENC_OUT_OFF 3735552ul
#define ENC_HID_OFF 37289984ul
#define LOSS_OFF    39387136ul

// Packed weight scratch (floats). All j-PAIR packed: jp in 0..63, j0=2jp, j1=2jp+1.
// Fused layer (per layer, 98304 floats):
//   WA [k128][jp64][4] = {whr(j0),whr(j1),whz(j0),whz(j1)}
//   WB [k128][jp64][4] = {whn(j0),whn(j1),wxr(j0),wxr(j1)}
//   WC [k128][jp64][4] = {wxz(j0),wxz(j1),wxn(j0),wxn(j1)}
// L0: HA [k128][jp][4]={hr0,hr1,hz0,hz1}  HB [k128][jp][2]={hn0,hn1}
//     XA [k4][jp][4]={xr0,xr1,xz0,xz1}    XB [k4][jp][2]={xn0,xn1}
// LIN1P [k128][jp][2] = {w(j0),w(j1)}
#define ENC_F    0
#define DEC_F    294912
#define ENC_L0HA 589824
#define ENC_L0HB 622592
#define ENC_L0XA 638976
#define ENC_L0XB 640000
#define DEC_L0HA 640512
#define DEC_L0HB 673280
#define DEC_L0XA 689664
#define DEC_L0XB 690688
#define LIN1P    691200
#define WT_TOTAL 707584

__device__ float g_wt[WT_TOTAL];

// ---------------- f32x2 helpers ----------------

typedef unsigned long long u64;

__device__ __forceinline__ void unpack2(u64 v, float& lo, float& hi)
{
    asm("mov.b64 {%0,%1},%2;" : "=f"(lo), "=f"(hi) : "l"(v));
}
__device__ __forceinline__ void ffma2(u64& d, u64 a, u64 b)
{
    asm("fma.rn.f32x2 %0,%1,%2,%3;" : "=l"(d) : "l"(a), "l"(b), "l"(d));
}
__device__ __forceinline__ u64 addx2(u64 a, u64 b)
{
    u64 r;
    asm("add.rn.f32x2 %0,%1,%2;" : "=l"(r) : "l"(a), "l"(b));
    return r;
}
__device__ __forceinline__ u64 ldu64(const float* p)
{
    return *(const u64*)p;
}

// ---------------- prep kernels ----------------

// fused layer pack: wih/whh are [3*128][128] row-major
__global__ void k_pack_fused(const float* __restrict__ wih,
                             const float* __restrict__ whh, int dstOff)
{
    for (int idx = blockIdx.x * blockDim.x + threadIdx.x; idx < 128 * 64;
         idx += gridDim.x * blockDim.x) {
        int k = idx >> 6, jp = idx & 63;
        int j0 = 2 * jp, j1 = j0 + 1;
        float* A = g_wt + dstOff + idx * 4;
        float* B = g_wt + dstOff + 32768 + idx * 4;
        float* C = g_wt + dstOff + 65536 + idx * 4;
        A[0] = whh[(0 * 128 + j0) * 128 + k];
        A[1] = whh[(0 * 128 + j1) * 128 + k];
        A[2] = whh[(1 * 128 + j0) * 128 + k];
        A[3] = whh[(1 * 128 + j1) * 128 + k];
        B[0] = whh[(2 * 128 + j0) * 128 + k];
        B[1] = whh[(2 * 128 + j1) * 128 + k];
        B[2] = wih[(0 * 128 + j0) * 128 + k];
        B[3] = wih[(0 * 128 + j1) * 128 + k];
        C[0] = wih[(1 * 128 + j0) * 128 + k];
        C[1] = wih[(1 * 128 + j1) * 128 + k];
        C[2] = wih[(2 * 128 + j0) * 128 + k];
        C[3] = wih[(2 * 128 + j1) * 128 + k];
    }
}

// L0 pack: whh0 [3*128][128], wih0 [3*128][4]
__global__ void k_pack_l0(const float* __restrict__ wih0,
                          const float* __restrict__ whh0,
                          int dHA, int dHB, int dXA, int dXB)
{
    for (int idx = blockIdx.x * blockDim.x + threadIdx.x; idx < 128 * 64;
         idx += gridDim.x * blockDim.x) {
        int k = idx >> 6, jp = idx & 63;
        int j0 = 2 * jp, j1 = j0 + 1;
        float* A = g_wt + dHA + idx * 4;
        float* B = g_wt + dHB + idx * 2;
        A[0] = whh0[(0 * 128 + j0) * 128 + k];
        A[1] = whh0[(0 * 128 + j1) * 128 + k];
        A[2] = whh0[(1 * 128 + j0) * 128 + k];
        A[3] = whh0[(1 * 128 + j1) * 128 + k];
        B[0] = whh0[(2 * 128 + j0) * 128 + k];
        B[1] = whh0[(2 * 128 + j1) * 128 + k];
        if (idx < 4 * 64) {
            int kx = idx >> 6;   // 0..3
            float* XA = g_wt + dXA + idx * 4;
            float* XB = g_wt + dXB + idx * 2;
            XA[0] = wih0[(0 * 128 + j0) * 4 + kx];
            XA[1] = wih0[(0 * 128 + j1) * 4 + kx];
            XA[2] = wih0[(1 * 128 + j0) * 4 + kx];
            XA[3] = wih0[(1 * 128 + j1) * 4 + kx];
            XB[0] = wih0[(2 * 128 + j0) * 4 + kx];
            XB[1] = wih0[(2 * 128 + j1) * 4 + kx];
        }
    }
}

// lin1_w [i][k] -> LIN1P [k][jp][2]
__global__ void k_pack_lin1(const float* __restrict__ src)
{
    for (int idx = blockIdx.x * blockDim.x + threadIdx.x; idx < 128 * 64;
         idx += gridDim.x * blockDim.x) {
        int k = idx >> 6, jp = idx & 63;
        g_wt[LIN1P + idx * 2]     = src[(2 * jp) * 128 + k];
        g_wt[LIN1P + idx * 2 + 1] = src[(2 * jp + 1) * 128 + k];
    }
}

__global__ void k_zero_loss(float* __restrict__ out)
{
    if (threadIdx.x == 0) out[LOSS_OFF] = 0.0f;
}

// ---------------- main kernel ----------------

__device__ __forceinline__ float sigf(float x)
{
    return 1.0f / (1.0f + __expf(-x));
}

__device__ __forceinline__ float tanhfast(float x)
{
    float t = __expf(2.0f * x);
    return 1.0f - 2.0f / (t + 1.0f);   // safe at +/- inf
}

// Pointwise update: acc pairs are {j0,j1}; writes duplicated h values.
// 8 batch elements per thread.
__device__ __forceinline__ void gru_pointwise(
    u64* ar, u64* az, u64* ain, u64* ahn, float* hsl, int j0, int bB)
{
    float* row0 = hsl + j0 * DUPW;
    float* row1 = hsl + (j0 + 1) * DUPW;
#pragma unroll
    for (int p = 0; p < 8; p++) {
        float r0, r1, z0, z1, i0, i1, n0, n1;
        unpack2(ar[p], r0, r1);
        unpack2(az[p], z0, z1);
        unpack2(ain[p], i0, i1);
        unpack2(ahn[p], n0, n1);
        int c = 2 * (bB + p);
        float h0 = row0[c], h1 = row1[c];
        float rr0 = sigf(r0), rr1 = sigf(r1);
        float zz0 = sigf(z0), zz1 = sigf(z1);
        float nn0 = tanhfast(fmaf(rr0, n0, i0));
        float nn1 = tanhfast(fmaf(rr1, n1, i1));
        float v0 = fmaf(zz0, h0 - nn0, nn0);
        float v1 = fmaf(zz1, h1 - nn1, nn1);
        row0[c] = v0; row0[c + 1] = v0;
        row1[c] = v1; row1[c + 1] = v1;
    }
}

// Fused GRU layer (input = prev layer h, duplicated smem layout).
__device__ __forceinline__ void gru_layer_f(
    const float* __restrict__ wf,
    const float* __restrict__ bih, const float* __restrict__ bhh,
    const float* __restrict__ xsd, float* __restrict__ hsd,
    int jp, int bB)
{
    const int j0 = 2 * jp;
    u64 ar[8], az[8], ain[8], ahn[8];
    {
        u64 br = addx2(ldu64(bih + j0), ldu64(bhh + j0));
        u64 bz = addx2(ldu64(bih + 128 + j0), ldu64(bhh + 128 + j0));
        u64 bi = ldu64(bih + 256 + j0);
        u64 bh = ldu64(bhh + 256 + j0);
#pragma unroll
        for (int p = 0; p < 8; p++) {
            ar[p] = br; az[p] = bz; ain[p] = bi; ahn[p] = bh;
        }
    }
    const float* pa = wf + jp * 4;
    const float* pb = wf + 32768 + jp * 4;
    const float* pc = wf + 65536 + jp * 4;
    ulonglong2 A = *(const ulonglong2*)pa;
    ulonglong2 B = *(const ulonglong2*)pb;
    ulonglong2 C = *(const ulonglong2*)pc;
#pragma unroll 2
    for (int k = 0; k < 128; k++) {
        ulonglong2 Ac = A, Bc = B, Cc = C;
        int kn = (k + 1) & 127;
        A = *(const ulonglong2*)(pa + kn * 256);
        B = *(const ulonglong2*)(pb + kn * 256);
        C = *(const ulonglong2*)(pc + kn * 256);
        const ulonglong2* hr = (const ulonglong2*)(hsd + k * DUPW + 2 * bB);
        const ulonglong2* xr = (const ulonglong2*)(xsd + k * DUPW + 2 * bB);
        ulonglong2 h01 = hr[0], h23 = hr[1], h45 = hr[2], h67 = hr[3];
        ulonglong2 x01 = xr[0], x23 = xr[1], x45 = xr[2], x67 = xr[3];
        u64 hd[8] = {h01.x, h01.y, h23.x, h23.y, h45.x, h45.y, h67.x, h67.y};
        u64 xd[8] = {x01.x, x01.y, x23.x, x23.y, x45.x, x45.y, x67.x, x67.y};
#pragma unroll
        for (int p = 0; p < 8; p++) {
            ffma2(ar[p], hd[p], Ac.x);
            ffma2(az[p], hd[p], Ac.y);
            ffma2(ahn[p], hd[p], Bc.x);
            ffma2(ar[p], xd[p], Bc.y);
            ffma2(az[p], xd[p], Cc.x);
            ffma2(ain[p], xd[p], Cc.y);
        }
    }
    __syncthreads();   // all reads of hsd done before overwrite
    gru_pointwise(ar, az, ain, ahn, hsd, j0, bB);
    __syncthreads();   // hsd ready for next layer
}

// Layer 0 (input dim 4 from duplicated x0s).
__device__ __forceinline__ void gru_layer_0(
    const float* __restrict__ ha, const float* __restrict__ hb,
    const float* __restrict__ xa, const float* __restrict__ xb,
    const float* __restrict__ bih, const float* __restrict__ bhh,
    const float* __restrict__ xsd, float* __restrict__ hsd,
    int jp, int bB)
{
    const int j0 = 2 * jp;
    u64 ar[8], az[8], ain[8], ahn[8];
    {
        u64 br = addx2(ldu64(bih + j0), ldu64(bhh + j0));
        u64 bz = addx2(ldu64(bih + 128 + j0), ldu64(bhh + 128 + j0));
        u64 bi = ldu64(bih + 256 + j0);
        u64 bh = ldu64(bhh + 256 + j0);
#pragma unroll
        for (int p = 0; p < 8; p++) {
            ar[p] = br; az[p] = bz; ain[p] = bi; ahn[p] = bh;
        }
    }
    const float* pa = ha + jp * 4;
    const float* pb = hb + jp * 2;
    ulonglong2 A = *(const ulonglong2*)pa;
    u64 Bv = ldu64(pb);
#pragma unroll 2
    for (int k = 0; k < 128; k++) {
        ulonglong2 Ac = A;
        u64 Bc = Bv;
        int kn = (k + 1) & 127;
        A = *(const ulonglong2*)(pa + kn * 256);
        Bv = ldu64(pb + kn * 128);
        const ulonglong2* hr = (const ulonglong2*)(hsd + k * DUPW + 2 * bB);
        ulonglong2 h01 = hr[0], h23 = hr[1], h45 = hr[2], h67 = hr[3];
        u64 hd[8] = {h01.x, h01.y, h23.x, h23.y, h45.x, h45.y, h67.x, h67.y};
#pragma unroll
        for (int p = 0; p < 8; p++) {
            ffma2(ar[p], hd[p], Ac.x);
            ffma2(az[p], hd[p], Ac.y);
            ffma2(ahn[p], hd[p], Bc);
        }
    }
#pragma unroll
    for (int k = 0; k < 4; k++) {
        ulonglong2 XA = *(const ulonglong2*)(xa + (k * 64 + jp) * 4);
        u64 XB = ldu64(xb + (k * 64 + jp) * 2);
        const ulonglong2* xr = (const ulonglong2*)(xsd + k * DUPW + 2 * bB);
        ulonglong2 x01 = xr[0], x23 = xr[1], x45 = xr[2], x67 = xr[3];
        u64 xd[8] = {x01.x, x01.y, x23.x, x23.y, x45.x, x45.y, x67.x, x67.y};
#pragma unroll
        for (int p = 0; p < 8; p++) {
            ffma2(ar[p], xd[p], XA.x);
            ffma2(az[p], xd[p], XA.y);
            ffma2(ain[p], xd[p], XB);
        }
    }
    __syncthreads();
    gru_pointwise(ar, az, ain, ahn, hsd, j0, bB);
    __syncthreads();
}

__global__ void __launch_bounds__(NTHREADS, 1) gru_main(
    const float* __restrict__ inp, const float* __restrict__ tgt,
    const float* __restrict__ enc_bih, const float* __restrict__ enc_bhh,
    const float* __restrict__ dec_bih, const float* __restrict__ dec_bhh,
    const float* __restrict__ lin1_b, const float* __restrict__ lin2_w,
    const float* __restrict__ lin2_b,
    float* __restrict__ out)
{
    extern __shared__ float sm[];
    float* hsd  = sm;                       // [4][128][DUPW] duplicated
    float* o1s  = sm + 4 * 128 * DUPW;      // [128][34] plain
    float* x0sd = o1s + 128 * 34;           // [4][DUPW] duplicated
    float* red  = x0sd + 4 * DUPW;          // [NTHREADS]

    const int tid  = threadIdx.x;
    const int lane = tid & 31;
    const int w    = tid >> 5;
    const int jp   = ((w & 1) << 5) | lane; // 0..63
    const int j0   = 2 * jp;
    const int bB   = (w >> 1) << 3;         // 8 batch elements per thread
    const int b0   = blockIdx.x * CB;

    for (int u = tid; u < 4 * 128 * DUPW; u += NTHREADS) hsd[u] = 0.0f;
    if (tid < CB * 4) {
        int b = tid >> 2, e = tid & 3;
        out[DEC_OUT_OFF + (size_t)(b0 + b) * 400 + e] =
            inp[(size_t)(b0 + b) * 256 + e];
    }
    __syncthreads();

    // ---------------- encoder: 64 steps ----------------
    for (int t = 0; t < 64; t++) {
        if (tid < CB * 4) {
            int b = tid >> 2, e = tid & 3;
            float xv = inp[(size_t)(b0 + b) * 256 + t * 4 + e];
            x0sd[e * DUPW + 2 * b]     = xv;
            x0sd[e * DUPW + 2 * b + 1] = xv;
        }
        __syncthreads();
        gru_layer_0(g_wt + ENC_L0HA, g_wt + ENC_L0HB,
                    g_wt + ENC_L0XA, g_wt + ENC_L0XB,
                    enc_bih, enc_bhh, x0sd, hsd, jp, bB);
#pragma unroll 1
        for (int l = 1; l < 4; l++) {
            gru_layer_f(g_wt + ENC_F + (l - 1) * 98304,
                        enc_bih + l * 384, enc_bhh + l * 384,
                        hsd + (l - 1) * 128 * DUPW, hsd + l * 128 * DUPW,
                        jp, bB);
        }
        const float* h3 = hsd + 3 * 128 * DUPW;
        for (int u = tid; u < CB * Hh; u += NTHREADS) {
            int b = u >> 7, k = u & 127;
            out[ENC_OUT_OFF + (size_t)(b0 + b) * 8192 + t * 128 + k] =
                h3[k * DUPW + 2 * b];
        }
        // no barrier: next write to hsd[3] / x0sd is many barriers away
    }
    // enc_hidden (L,B,H)
    for (int u = tid; u < 4 * CB * Hh; u += NTHREADS) {
        int l = u >> 12, r = u & 4095, b = r >> 7, k = r & 127;
        out[ENC_HID_OFF + (size_t)l * 524288 + (size_t)(b0 + b) * 128 + k] =
            hsd[l * 128 * DUPW + k * DUPW + 2 * b];
    }

    // ---------------- decoder: 99 steps ----------------
    float lossAcc = 0.0f;
    for (int s = 0; s < 99; s++) {
        if (tid < CB * 4) {
            int b = tid >> 2, e = tid & 3;
            float xv = (s == 0) ? inp[(size_t)(b0 + b) * 256 + e]
                                : tgt[(size_t)(b0 + b) * 400 + s * 4 + e];
            x0sd[e * DUPW + 2 * b]     = xv;
            x0sd[e * DUPW + 2 * b + 1] = xv;
        }
        __syncthreads();
        gru_layer_0(g_wt + DEC_L0HA, g_wt + DEC_L0HB,
                    g_wt + DEC_L0XA, g_wt + DEC_L0XB,
                    dec_bih, dec_bhh, x0sd, hsd, jp, bB);
#pragma unroll 1
        for (int l = 1; l < 4; l++) {
            gru_layer_f(g_wt + DEC_F + (l - 1) * 98304,
                        dec_bih + l * 384, dec_bhh + l * 384,
                        hsd + (l - 1) * 128 * DUPW, hsd + l * 128 * DUPW,
                        jp, bB);
        }
        // lin1 + relu -> o1s (plain layout)
        {
            u64 acc[8];
            u64 bi = ldu64(lin1_b + j0);
#pragma unroll
            for (int p = 0; p < 8; p++) acc[p] = bi;
            const float* top = hsd + 3 * 128 * DUPW;
            const float* pw = g_wt + LIN1P + jp * 2;
            u64 wv = ldu64(pw);
#pragma unroll 2
            for (int k = 0; k < 128; k++) {
                u64 wc = wv;
                int kn = (k + 1) & 127;
                wv = ldu64(pw + kn * 128);
                const ulonglong2* tr =
                    (const ulonglong2*)(top + k * DUPW + 2 * bB);
                ulonglong2 t01 = tr[0], t23 = tr[1], t45 = tr[2], t67 = tr[3];
                u64 td[8] = {t01.x, t01.y, t23.x, t23.y,
                             t45.x, t45.y, t67.x, t67.y};
#pragma unroll
                for (int p = 0; p < 8; p++)
                    ffma2(acc[p], td[p], wc);
            }
#pragma unroll
            for (int p = 0; p < 8; p++) {
                float a0, a1;
                unpack2(acc[p], a0, a1);
                o1s[j0 * 34 + bB + p]       = fmaxf(a0, 0.0f);
                o1s[(j0 + 1) * 34 + bB + p] = fmaxf(a1, 0.0f);
            }
        }
        __syncthreads();
        // lin2 + loss + store
        if (tid < CB * 4) {
            int b = tid >> 2, e = tid & 3;
            float acc = lin2_b[e];
#pragma unroll 4
            for (int i = 0; i < Hh; i++)
                acc = fmaf(o1s[i * 34 + b], lin2_w[e * Hh + i], acc);
            float y = tgt[(size_t)(b0 + b) * 400 + (s + 1) * 4 + e];
            float d = acc - y;
            lossAcc += d * d;
            out[DEC_OUT_OFF + (size_t)(b0 + b) * 400 + (s + 1) * 4 + e] = acc;
        }
        __syncthreads();   // o1s reads done before next step's lin1 writes
    }
    // dec_hidden (L,B,H)
    for (int u = tid; u < 4 * CB * Hh; u += NTHREADS) {
        int l = u >> 12, r = u & 4095, b = r >> 7, k = r & 127;
        out[DEC_HID_OFF + (size_t)l * 524288 + (size_t)(b0 + b) * 128 + k] =
            hsd[l * 128 * DUPW + k * DUPW + 2 * b];
    }

    // loss reduction
    red[tid] = lossAcc;
    __syncthreads();
    for (int s2 = NTHREADS / 2; s2 > 0; s2 >>= 1) {
        if (tid < s2) red[tid] += red[tid + s2];
        __syncthreads();
    }
    if (tid == 0) atomicAdd(out + LOSS_OFF, red[0] * (1.0f / 16384.0f));
}

// ---------------- launch ----------------

extern "C" void kernel_launch(void* const* d_in, const int* in_sizes, int n_in,
                              void* d_out, int out_size)
{
    const float* inp      = (const float*)d_in[0];
    const float* tgt      = (const float*)d_in[1];
    const float* enc_wih0 = (const float*)d_in[2];
    const float* enc_whh0 = (const float*)d_in[3];
    const float* enc_wih  = (const float*)d_in[4];
    const float* enc_whh  = (const float*)d_in[5];
    const float* enc_bih  = (const float*)d_in[6];
    const float* enc_bhh  = (const float*)d_in[7];
    const float* dec_wih0 = (const float*)d_in[8];
    const float* dec_whh0 = (const float*)d_in[9];
    const float* dec_wih  = (const float*)d_in[10];
    const float* dec_whh  = (const float*)d_in[11];
    const float* dec_bih  = (const float*)d_in[12];
    const float* dec_bhh  = (const float*)d_in[13];
    const float* lin1_w   = (const float*)d_in[14];
    const float* lin1_b   = (const float*)d_in[15];
    const float* lin2_w   = (const float*)d_in[16];
    const float* lin2_b   = (const float*)d_in[17];
    float* out = (float*)d_out;

    const int smemBytes =
        (4 * 128 * DUPW + 128 * 34 + 4 * DUPW + NTHREADS) * 4;
    cudaFuncSetAttribute(gru_main, cudaFuncAttributeMaxDynamicSharedMemorySize,
                         smemBytes);

    k_zero_loss<<<1, 32>>>(out);

    k_pack_l0<<<16, 512>>>(enc_wih0, enc_whh0,
                           ENC_L0HA, ENC_L0HB, ENC_L0XA, ENC_L0XB);
    k_pack_l0<<<16, 512>>>(dec_wih0, dec_whh0,
                           DEC_L0HA, DEC_L0HB, DEC_L0XA, DEC_L0XB);
    for (int l = 0; l < 3; l++) {
        k_pack_fused<<<16, 512>>>(enc_wih + l * 49152, enc_whh + l * 49152,
                                  ENC_F + l * 98304);
        k_pack_fused<<<16, 512>>>(dec_wih + l * 49152, dec_whh + l * 49152,
                                  DEC_F + l * 98304);
    }
    k_pack_lin1<<<16, 512>>>(lin1_w);

    gru_main<<<NBLOCKS, NTHREADS, smemBytes>>>(
        inp, tgt, enc_bih, enc_bhh, dec_bih, dec_bhh,
        lin1_b, lin2_w, lin2_b, out);
}

// round 17
// speedup vs baseline: 2.0393x; 2.0393x over previous
#include <cuda_runtime.h>
#include <math.h>
#include <stdint.h>

#define NTHREADS 256
#define NBLOCKS  128

// out offsets (floats)
#define DEC_OUT_OFF 0ul
#define DEC_HID_OFF 1638400ul
#define ENC_OUT_OFF 3735552ul
#define ENC_HID_OFF 37289984ul
#define LOSS_OFF    39387136ul

// g_wt stream bases (u32 units)
#define ENC_L0S 0
#define DEC_L0S 55296
#define ENC_FS  110592
#define DEC_FS  405504
#define LIN1S   700416
#define WT_TOT  716800
__device__ __align__(16) unsigned g_wt[WT_TOT];

// smem u32 offsets
#define XVAR 8712             // hi->lo variant stride
#define XPL(p) ((p)*2112)     // h plane p (64 k2-rows x 33)
#define XZP  8448             // x0 plane (8 k2-rows x 33)
#define GS   17424            // gate buffer: 4 x [128][33] fp32
#define GGATE 4224
#define REDU 34320
#define SMU_TOT 34576
#define SM_BYTES (SMU_TOT*4)

__device__ __forceinline__ unsigned short bfb(float v){
    unsigned u = __float_as_uint(v);
    unsigned r = (u + 0x7FFFu + ((u >> 16) & 1u)) >> 16;
    return (unsigned short)r;
}
__device__ __forceinline__ float bf2f(unsigned s){ return __uint_as_float(s << 16); }
__device__ __forceinline__ unsigned packbf(float a, float b){
    return ((unsigned)bfb(b) << 16) | (unsigned)bfb(a);
}
__device__ __forceinline__ float sigf(float x){ return 1.0f/(1.0f+__expf(-x)); }
__device__ __forceinline__ float tanhfast(float x){ float t=__expf(2.0f*x); return 1.0f-2.0f/(t+1.0f); }

__device__ __forceinline__ void domma(float* c, uint4 a, unsigned b0, unsigned b1){
    asm volatile(
        "mma.sync.aligned.m16n8k16.row.col.f32.bf16.bf16.f32 "
        "{%0,%1,%2,%3},{%4,%5,%6,%7},{%8,%9},{%0,%1,%2,%3};"
        : "+f"(c[0]), "+f"(c[1]), "+f"(c[2]), "+f"(c[3])
        : "r"(a.x), "r"(a.y), "r"(a.z), "r"(a.w), "r"(b0), "r"(b1));
}

// ---------------- prep kernels ----------------
// A-fragment streams. Virtual rows: [r(128) | z(128) | nx(128) | nh(128)].
// warp w owns vrows [w*64, w*64+64): vg=w>>1, j=(w&1)*64 + mt*16 + g + (rg&1)*8
// col = ks*16 + t*2 + (rg>>1)*8 + half

__global__ void k_pack_f(const float* __restrict__ wih, const float* __restrict__ whh, int base)
{
    for (int idx = blockIdx.x*blockDim.x + threadIdx.x; idx < 98304; idx += gridDim.x*blockDim.x) {
        int bw = idx >> 10, rem = idx & 1023, var = rem >> 9, mt = (rem >> 7) & 3,
            lane = (rem >> 2) & 31, rg = rem & 3;
        int w, ks;
        if (bw < 64) { w = bw >> 4; ks = bw & 15; }
        else { int b2 = bw - 64; w = 4 + (b2 >> 3); ks = b2 & 7; }
        int g = lane >> 2, t = lane & 3;
        int vg = w >> 1, j = ((w & 1) << 6) + mt*16 + g + ((rg & 1) << 3);
        int cb = ks*16 + t*2 + ((rg >> 1) << 3);
        float e[2];
        for (int hf = 0; hf < 2; hf++) {
            int col = cb + hf;
            float v;
            if (vg < 2)      v = (col < 128) ? wih[(vg*128+j)*128 + col] : whh[(vg*128+j)*128 + col - 128];
            else if (vg == 2) v = wih[(256+j)*128 + col];
            else              v = whh[(256+j)*128 + col];
            if (var) { float hi = bf2f(bfb(v)); v = v - hi; }
            e[hf] = v;
        }
        g_wt[base + idx] = packbf(e[0], e[1]);
    }
}

// L0: rz warps ks0 = x part (16 cols, 4 real), ks1-8 = h; nx: 1 kstep x; nh: 8 ksteps h.
__global__ void k_pack_l0(const float* __restrict__ wih0, const float* __restrict__ whh0, int base)
{
    for (int idx = blockIdx.x*blockDim.x + threadIdx.x; idx < 55296; idx += gridDim.x*blockDim.x) {
        int bw = idx >> 10, rem = idx & 1023, var = rem >> 9, mt = (rem >> 7) & 3,
            lane = (rem >> 2) & 31, rg = rem & 3;
        int w, ks;
        if (bw < 36)      { w = bw / 9; ks = bw % 9; }
        else if (bw < 38) { w = 4 + (bw - 36); ks = 0; }
        else              { int b2 = bw - 38; w = 6 + (b2 >> 3); ks = b2 & 7; }
        int g = lane >> 2, t = lane & 3;
        int vg = w >> 1, j = ((w & 1) << 6) + mt*16 + g + ((rg & 1) << 3);
        int c16 = t*2 + ((rg >> 1) << 3);
        float e[2];
        for (int hf = 0; hf < 2; hf++) {
            int col = c16 + hf;
            float v;
            if (vg < 2) {
                if (ks == 0) v = (col < 4) ? wih0[(vg*128+j)*4 + col] : 0.0f;
                else         v = whh0[(vg*128+j)*128 + (ks-1)*16 + col];
            } else if (vg == 2) v = (col < 4) ? wih0[(256+j)*4 + col] : 0.0f;
            else                v = whh0[(256+j)*128 + ks*16 + col];
            if (var) { float hi = bf2f(bfb(v)); v = v - hi; }
            e[hf] = v;
        }
        g_wt[base + idx] = packbf(e[0], e[1]);
    }
}

__global__ void k_pack_lin1(const float* __restrict__ w1)
{
    for (int idx = blockIdx.x*blockDim.x + threadIdx.x; idx < 16384; idx += gridDim.x*blockDim.x) {
        int bw = idx >> 8, rem = idx & 255, var = rem >> 7, lane = (rem >> 2) & 31, rg = rem & 3;
        int w = bw >> 3, ks = bw & 7;
        int g = lane >> 2, t = lane & 3;
        int j = w*16 + g + ((rg & 1) << 3);
        int cb = ks*16 + t*2 + ((rg >> 1) << 3);
        float e[2];
        for (int hf = 0; hf < 2; hf++) {
            float v = w1[j*128 + cb + hf];
            if (var) { float hi = bf2f(bfb(v)); v = v - hi; }
            e[hf] = v;
        }
        g_wt[LIN1S + idx] = packbf(e[0], e[1]);
    }
}

__global__ void k_zero_loss(float* __restrict__ out){ if (threadIdx.x == 0) out[LOSS_OFF] = 0.0f; }

// ---------------- gemm core ----------------
// MODE 0=L0, 1=fused layer, 2=lin1
template<int MODE>
__device__ __forceinline__ void gemm_acc(const unsigned* __restrict__ LB,
        const unsigned* __restrict__ smu, int pPrev, int pCur,
        float acc[][4][4], int w, int lane, const int* cs)
{
    const int NMT = (MODE == 2) ? 1 : 4;
    int t = lane & 3;
    int nks = (MODE == 1) ? ((w < 4) ? 16 : 8)
            : (MODE == 0) ? ((w < 4) ? 9 : ((w < 6) ? 1 : 8)) : 8;
    for (int ks = 0; ks < nks; ks++) {
        int bwv, bpl, bk2;
        if (MODE == 1) {
            bwv = (w < 4) ? (w*16 + ks) : (64 + ((w-4) << 3) + ks);
            if (w < 4)      { bpl = (ks < 8) ? pPrev : pCur; bk2 = ((ks & 7) << 3) + t; }
            else if (w < 6) { bpl = pPrev; bk2 = (ks << 3) + t; }
            else            { bpl = pCur;  bk2 = (ks << 3) + t; }
        } else if (MODE == 0) {
            if (w < 4) { bwv = w*9 + ks;
                         if (ks == 0) { bpl = pPrev; bk2 = t; }
                         else         { bpl = pCur;  bk2 = ((ks-1) << 3) + t; } }
            else if (w < 6) { bwv = 36 + (w - 4); bpl = pPrev; bk2 = t; }
            else            { bwv = 38 + ((w-6) << 3) + ks; bpl = pCur; bk2 = (ks << 3) + t; }
        } else { bwv = (w << 3) + ks; bpl = pPrev; bk2 = (ks << 3) + t; }

        const unsigned* blk = LB + ((MODE == 2) ? (bwv << 8) : (bwv << 10));
        const int VS = (MODE == 2) ? 128 : 512;
        uint4 Ah[NMT], Al[NMT];
#pragma unroll
        for (int mt = 0; mt < NMT; mt++) {
            Ah[mt] = *(const uint4*)(blk + mt*128 + lane*4);
            Al[mt] = *(const uint4*)(blk + VS + mt*128 + lane*4);
        }
        unsigned Bh0[4], Bh1[4], Bl0[4], Bl1[4];
        const unsigned* ph = smu + bpl;
        const unsigned* pl = ph + XVAR;
        int r0 = bk2*33, r1 = r0 + 132;
#pragma unroll
        for (int nt = 0; nt < 4; nt++) {
            int c0 = cs[nt];
            Bh0[nt] = ph[r0 + c0]; Bh1[nt] = ph[r1 + c0];
            Bl0[nt] = pl[r0 + c0]; Bl1[nt] = pl[r1 + c0];
        }
#pragma unroll
        for (int mt = 0; mt < NMT; mt++)
#pragma unroll
            for (int nt = 0; nt < 4; nt++) {
                domma(acc[mt][nt], Ah[mt], Bh0[nt], Bh1[nt]);
                domma(acc[mt][nt], Ah[mt], Bl0[nt], Bl1[nt]);
                domma(acc[mt][nt], Al[mt], Bh0[nt], Bh1[nt]);
            }
    }
}

template<int MODE>
__device__ __forceinline__ void store_acc(float* smf, float acc[][4][4], int w, int lane)
{
    const int NMT = (MODE == 2) ? 1 : 4;
    int g = lane >> 2, t = lane & 3;
    int base = (MODE == 2) ? (GS + (w*16)*33)
                           : (GS + (w >> 1)*GGATE + (((w & 1) << 6))*33);
#pragma unroll
    for (int mt = 0; mt < NMT; mt++)
#pragma unroll
        for (int nt = 0; nt < 4; nt++) {
            float* c = acc[mt][nt];
            int r = mt*16 + g, col = nt*8 + t*2;
            smf[base + r*33 + col]       = c[0];
            smf[base + r*33 + col + 1]   = c[1];
            smf[base + (r+8)*33 + col]     = c[2];
            smf[base + (r+8)*33 + col + 1] = c[3];
        }
}

// GRU pointwise: gates from GS buffer, h plane (split bf16) updated in place.
__device__ __forceinline__ void pointwise(unsigned* smu, float* smf, int tid,
        const float* __restrict__ bih, const float* __restrict__ bhh,
        int pbase, float* __restrict__ gout)
{
    int j = tid & 127, bh = tid >> 7;
    float br = bih[j] + bhh[j];
    float bz = bih[128 + j] + bhh[128 + j];
    float bi = bih[256 + j], bn = bhh[256 + j];
    int k2 = j >> 1, hs = j & 1;
    unsigned* Ph = smu + pbase;
    unsigned* Pl = Ph + XVAR;
    int arow = k2*33;
    for (int b = bh*16; b < bh*16 + 16; b++) {
        float R  = smf[GS + 0*GGATE + j*33 + b];
        float Z  = smf[GS + 1*GGATE + j*33 + b];
        float NX = smf[GS + 2*GGATE + j*33 + b];
        float NH = smf[GS + 3*GGATE + j*33 + b];
        int csv = (b + ((k2 & 3) << 3)) & 31;
        int a = arow + csv;
        unsigned uh = Ph[a], ul = Pl[a];
        float hold = bf2f((uh >> (hs*16)) & 0xFFFFu) + bf2f((ul >> (hs*16)) & 0xFFFFu);
        float r = sigf(R + br), z = sigf(Z + bz);
        float n = tanhfast(NX + bi + r*(NH + bn));
        float h = fmaf(z, hold - n, n);
        unsigned short hb = bfb(h);
        unsigned short lb = bfb(h - bf2f(hb));
        ((unsigned short*)(Ph + a))[hs] = hb;
        ((unsigned short*)(Pl + a))[hs] = lb;
        if (gout) gout[(size_t)b*8192 + j] = h;
    }
}

template<int MODE>
__device__ __forceinline__ void layer_full(const unsigned* LB, unsigned* smu, float* smf,
        int pPrev, int pCur, const float* bih, const float* bhh,
        float* gout, int tid, int w, int lane, const int* cs)
{
    float acc[4][4][4];
#pragma unroll
    for (int mt = 0; mt < 4; mt++)
#pragma unroll
        for (int nt = 0; nt < 4; nt++)
#pragma unroll
            for (int i = 0; i < 4; i++) acc[mt][nt][i] = 0.0f;
    gemm_acc<MODE>(LB, smu, pPrev, pCur, acc, w, lane, cs);
    store_acc<MODE>(smf, acc, w, lane);
    __syncthreads();
    pointwise(smu, smf, tid, bih, bhh, pCur, gout);
    __syncthreads();
}

__global__ void __launch_bounds__(NTHREADS, 1) gru_main(
    const float* __restrict__ inp, const float* __restrict__ tgt,
    const float* __restrict__ enc_bih, const float* __restrict__ enc_bhh,
    const float* __restrict__ dec_bih, const float* __restrict__ dec_bhh,
    const float* __restrict__ lin1_b, const float* __restrict__ lin2_w,
    const float* __restrict__ lin2_b, float* __restrict__ out)
{
    extern __shared__ unsigned smu[];
    float* smf = (float*)smu;
    const int tid = threadIdx.x;
    const int w = tid >> 5, lane = tid & 31;
    const int g = lane >> 2, t = lane & 3;
    const size_t b0 = (size_t)blockIdx.x * 32;
    int cs[4];
#pragma unroll
    for (int nt = 0; nt < 4; nt++) cs[nt] = ((nt*8 + g) + 8*t) & 31;

    for (int u = tid; u < 2*XVAR; u += NTHREADS) smu[u] = 0u;   // zero planes
    if (tid < 128) {
        int b = tid >> 2, e = tid & 3;
        out[DEC_OUT_OFF + (b0 + b)*400 + e] = inp[(b0 + b)*256 + e];
    }
    __syncthreads();

    // ---------------- encoder ----------------
    for (int tt = 0; tt < 64; tt++) {
        if (tid < 128) {
            int b = tid >> 2, e = tid & 3;
            float v = inp[(b0 + b)*256 + tt*4 + e];
            int k2 = e >> 1, hs = e & 1;
            int csv = (b + (k2 << 3)) & 31;
            int a = XZP + k2*33 + csv;
            unsigned short hb = bfb(v);
            unsigned short lb = bfb(v - bf2f(hb));
            ((unsigned short*)(smu + a))[hs] = hb;
            ((unsigned short*)(smu + a + XVAR))[hs] = lb;
        }
        __syncthreads();
        layer_full<0>(g_wt + ENC_L0S, smu, smf, XZP, XPL(0),
                      enc_bih, enc_bhh, 0, tid, w, lane, cs);
#pragma unroll 1
        for (int l = 1; l < 4; l++)
            layer_full<1>(g_wt + ENC_FS + (l-1)*98304, smu, smf, XPL(l-1), XPL(l),
                          enc_bih + l*384, enc_bhh + l*384,
                          (l == 3) ? (out + ENC_OUT_OFF + b0*8192 + (size_t)tt*128) : 0,
                          tid, w, lane, cs);
    }
    // enc_hidden
    for (int u = tid; u < 16384; u += NTHREADS) {
        int l = u >> 12, b = (u >> 7) & 31, j = u & 127;
        int k2 = j >> 1, hs = j & 1;
        int csv = (b + ((k2 & 3) << 3)) & 31;
        int a = XPL(l) + k2*33 + csv;
        float h = bf2f((smu[a] >> (hs*16)) & 0xFFFFu) +
                  bf2f((smu[a + XVAR] >> (hs*16)) & 0xFFFFu);
        out[ENC_HID_OFF + (size_t)l*524288 + (b0 + b)*128 + j] = h;
    }

    // ---------------- decoder ----------------
    float lossAcc = 0.0f;
    for (int s = 0; s < 99; s++) {
        if (tid < 128) {
            int b = tid >> 2, e = tid & 3;
            float v = (s == 0) ? inp[(b0 + b)*256 + e] : tgt[(b0 + b)*400 + s*4 + e];
            int k2 = e >> 1, hs = e & 1;
            int csv = (b + (k2 << 3)) & 31;
            int a = XZP + k2*33 + csv;
            unsigned short hb = bfb(v);
            unsigned short lb = bfb(v - bf2f(hb));
            ((unsigned short*)(smu + a))[hs] = hb;
            ((unsigned short*)(smu + a + XVAR))[hs] = lb;
        }
        __syncthreads();
        layer_full<0>(g_wt + DEC_L0S, smu, smf, XZP, XPL(0),
                      dec_bih, dec_bhh, 0, tid, w, lane, cs);
#pragma unroll 1
        for (int l = 1; l < 4; l++)
            layer_full<1>(g_wt + DEC_FS + (l-1)*98304, smu, smf, XPL(l-1), XPL(l),
                          dec_bih + l*384, dec_bhh + l*384, 0, tid, w, lane, cs);
        // lin1 via mma (output rows into GS gate-0 buffer)
        {
            float acc[1][4][4];
#pragma unroll
            for (int nt = 0; nt < 4; nt++)
#pragma unroll
                for (int i = 0; i < 4; i++) acc[0][nt][i] = 0.0f;
            gemm_acc<2>(g_wt + LIN1S, smu, XPL(3), 0, acc, w, lane, cs);
            store_acc<2>(smf, acc, w, lane);
        }
        __syncthreads();
        // lin2 + loss
        if (tid < 128) {
            int b = tid >> 2, e = tid & 3;
            float a2 = lin2_b[e];
#pragma unroll 4
            for (int i = 0; i < 128; i++) {
                float o = fmaxf(smf[GS + i*33 + b] + lin1_b[i], 0.0f);
                a2 = fmaf(o, lin2_w[e*128 + i], a2);
            }
            float y = tgt[(b0 + b)*400 + (s + 1)*4 + e];
            float d = a2 - y;
            lossAcc += d*d;
            out[DEC_OUT_OFF + (b0 + b)*400 + (s + 1)*4 + e] = a2;
        }
        __syncthreads();
    }
    // dec_hidden
    for (int u = tid; u < 16384; u += NTHREADS) {
        int l = u >> 12, b = (u >> 7) & 31, j = u & 127;
        int k2 = j >> 1, hs = j & 1;
        int csv = (b + ((k2 & 3) << 3)) & 31;
        int a = XPL(l) + k2*33 + csv;
        float h = bf2f((smu[a] >> (hs*16)) & 0xFFFFu) +
                  bf2f((smu[a + XVAR] >> (hs*16)) & 0xFFFFu);
        out[DEC_HID_OFF + (size_t)l*524288 + (b0 + b)*128 + j] = h;
    }

    smf[REDU + tid] = lossAcc;
    __syncthreads();
    for (int s2 = NTHREADS/2; s2 > 0; s2 >>= 1) {
        if (tid < s2) smf[REDU + tid] += smf[REDU + tid + s2];
        __syncthreads();
    }
    if (tid == 0) atomicAdd(out + LOSS_OFF, smf[REDU] * (1.0f/16384.0f));
}

// ---------------- launch ----------------
extern "C" void kernel_launch(void* const* d_in, const int* in_sizes, int n_in,
                              void* d_out, int out_size)
{
    const float* inp      = (const float*)d_in[0];
    const float* tgt      = (const float*)d_in[1];
    const float* enc_wih0 = (const float*)d_in[2];
    const float* enc_whh0 = (const float*)d_in[3];
    const float* enc_wih  = (const float*)d_in[4];
    const float* enc_whh  = (const float*)d_in[5];
    const float* enc_bih  = (const float*)d_in[6];
    const float* enc_bhh  = (const float*)d_in[7];
    const float* dec_wih0 = (const float*)d_in[8];
    const float* dec_whh0 = (const float*)d_in[9];
    const float* dec_wih  = (const float*)d_in[10];
    const float* dec_whh  = (const float*)d_in[11];
    const float* dec_bih  = (const float*)d_in[12];
    const float* dec_bhh  = (const float*)d_in[13];
    const float* lin1_w   = (const float*)d_in[14];
    const float* lin1_b   = (const float*)d_in[15];
    const float* lin2_w   = (const float*)d_in[16];
    const float* lin2_b   = (const float*)d_in[17];
    float* out = (float*)d_out;

    cudaFuncSetAttribute(gru_main, cudaFuncAttributeMaxDynamicSharedMemorySize, SM_BYTES);

    k_zero_loss<<<1, 32>>>(out);
    k_pack_l0<<<108, 512>>>(enc_wih0, enc_whh0, ENC_L0S);
    k_pack_l0<<<108, 512>>>(dec_wih0, dec_whh0, DEC_L0S);
    for (int l = 0; l < 3; l++) {
        k_pack_f<<<96, 512>>>(enc_wih + l*49152, enc_whh + l*49152, ENC_FS + l*98304);
        k_pack_f<<<96, 512>>>(dec_wih + l*49152, dec_whh + l*49152, DEC_FS + l*98304);
    }
    k_pack_lin1<<<32, 512>>>(lin1_w);

    gru_main<<<NBLOCKS, NTHREADS, SM_BYTES>>>(
        inp, tgt, enc_bih, enc_bhh, dec_bih, dec_bhh,
        lin1_b, lin2_w, lin2_b, out);
}